// round 1
// baseline (speedup 1.0000x reference)
#include <cuda_runtime.h>
#include <math.h>

#define NS  1024
#define XD  128
#define HID 256

// scratch (allocation-free rule: __device__ globals)
__device__ float g_pxT[HID * NS];   // [k][j] : px transposed
__device__ float g_pybT[HID * NS];  // [k][i] : (y@W1y + b1) transposed
__device__ float g_diag[NS];        // T1[i,i]
__device__ float g_e[NS];           // exp(lse_i - ln N)

// ---------------------------------------------------------------------------
// GEMM: C_T[h][n] = sum_d A[n][d] * W1[z*128 + d][h]   (+ b1[h] when z==1)
// block tile 64h x 64n, 256 threads, thread tile 4x4 (strided by 16)
// ---------------------------------------------------------------------------
__global__ __launch_bounds__(256) void gemm_kernel(
    const float* __restrict__ X, const float* __restrict__ Y,
    const float* __restrict__ W1, const float* __restrict__ b1)
{
    const int z  = blockIdx.z;
    const float* A = z ? Y : X;
    float* C = z ? g_pybT : g_pxT;
    const int h0 = blockIdx.y * 64;
    const int n0 = blockIdx.x * 64;
    const int t  = threadIdx.x;
    const int tx = t & 15;   // n dim
    const int ty = t >> 4;   // h dim

    __shared__ float xs[64][65];  // [n][d], pad 65 for conflict-free column reads
    __shared__ float ws[64][64];  // [d][h]

    float acc[4][4];
#pragma unroll
    for (int i = 0; i < 4; i++)
#pragma unroll
        for (int j = 0; j < 4; j++) acc[i][j] = 0.f;

    for (int k0 = 0; k0 < XD; k0 += 64) {
        __syncthreads();
        // load xs: 64n x 64d (scalar, coalesced)
#pragma unroll
        for (int r = 0; r < 16; r++) {
            int f = t + 256 * r;
            int n = f >> 6, d = f & 63;
            xs[n][d] = A[(n0 + n) * XD + k0 + d];
        }
        // load ws: 64d x 64h (vectorized, coalesced)
#pragma unroll
        for (int r = 0; r < 4; r++) {
            int f = t + 256 * r;
            int d = f >> 4, h4 = (f & 15) * 4;
            float4 v = *(const float4*)&W1[(z * XD + k0 + d) * HID + h0 + h4];
            *(float4*)&ws[d][h4] = v;
        }
        __syncthreads();
#pragma unroll 8
        for (int d = 0; d < 64; d++) {
            float a[4], b[4];
#pragma unroll
            for (int c = 0; c < 4; c++) a[c] = ws[d][ty + 16 * c];
#pragma unroll
            for (int c = 0; c < 4; c++) b[c] = xs[tx + 16 * c][d];
#pragma unroll
            for (int i = 0; i < 4; i++)
#pragma unroll
                for (int j = 0; j < 4; j++)
                    acc[i][j] = fmaf(a[i], b[j], acc[i][j]);
        }
    }

#pragma unroll
    for (int i = 0; i < 4; i++) {
        int h = h0 + ty + 16 * i;
        float bias = z ? b1[h] : 0.f;
#pragma unroll
        for (int j = 0; j < 4; j++) {
            int n = n0 + tx + 16 * j;
            C[h * NS + n] = acc[i][j] + bias;
        }
    }
}

// ---------------------------------------------------------------------------
// Pair kernel: block = 8 rows (i), all 1024 cols (j). 256 threads, each owns
// 8i x 4j accumulators. px streamed from L2 via LDG.128 direct to registers.
// Computes online logsumexp over j per i, and captures diagonal T1[i,i].
// ---------------------------------------------------------------------------
__global__ __launch_bounds__(256) void pair_kernel(
    const float* __restrict__ W2, const float* __restrict__ b2)
{
    __shared__ float sm_py[HID][8];   // pyb_T[k][ii]
    __shared__ float sm_w2[HID];
    __shared__ float red_m[8][8];     // [warp][ii]
    __shared__ float red_s[8][8];

    const int t  = threadIdx.x;
    const int i0 = blockIdx.x * 8;

    // load the 8 pyb columns for this block (one-time)
#pragma unroll
    for (int r = 0; r < 8; r++) {
        int f = t + 256 * r;          // 2048 values
        int k = f >> 3, ii = f & 7;
        sm_py[k][ii] = g_pybT[k * NS + i0 + ii];
    }
    sm_w2[t] = W2[t];                 // blockDim == HID == 256
    __syncthreads();

    float acc[8][4];
#pragma unroll
    for (int ii = 0; ii < 8; ii++)
#pragma unroll
        for (int jj = 0; jj < 4; jj++) acc[ii][jj] = 0.f;

    const float4* px4 = (const float4*)g_pxT;  // row k: NS/4 float4
    const int jb = t;                          // this thread's float4 column

#pragma unroll 1
    for (int k0 = 0; k0 < HID; k0 += 8) {
        float4 p[8];
#pragma unroll
        for (int kk = 0; kk < 8; kk++)
            p[kk] = px4[(k0 + kk) * (NS / 4) + jb];

#pragma unroll
        for (int kk = 0; kk < 8; kk++) {
            const float w  = sm_w2[k0 + kk];
            const float4 A0 = *(const float4*)&sm_py[k0 + kk][0];
            const float4 A1 = *(const float4*)&sm_py[k0 + kk][4];
            const float av[8] = {A0.x, A0.y, A0.z, A0.w, A1.x, A1.y, A1.z, A1.w};
            const float pv[4] = {p[kk].x, p[kk].y, p[kk].z, p[kk].w};
#pragma unroll
            for (int ii = 0; ii < 8; ii++) {
#pragma unroll
                for (int jj = 0; jj < 4; jj++) {
                    float v = av[ii] + pv[jj];
                    acc[ii][jj] = fmaf(fmaxf(v, 0.f), w, acc[ii][jj]);
                }
            }
        }
    }

    // epilogue: T1 = acc + b2 - 1 ; diagonal capture + per-i logsumexp
    const float bm1 = b2[0] - 1.0f;
    float m[8], s[8];
#pragma unroll
    for (int ii = 0; ii < 8; ii++) {
        float v[4];
#pragma unroll
        for (int jj = 0; jj < 4; jj++) v[jj] = acc[ii][jj] + bm1;
        const int ig = i0 + ii;
#pragma unroll
        for (int jj = 0; jj < 4; jj++)
            if (4 * t + jj == ig) g_diag[ig] = v[jj];
        float mm = fmaxf(fmaxf(v[0], v[1]), fmaxf(v[2], v[3]));
        float ss = expf(v[0] - mm) + expf(v[1] - mm) +
                   expf(v[2] - mm) + expf(v[3] - mm);
        m[ii] = mm; s[ii] = ss;
    }

    // warp-level (m,s) merge
#pragma unroll
    for (int off = 16; off > 0; off >>= 1) {
#pragma unroll
        for (int ii = 0; ii < 8; ii++) {
            float om = __shfl_xor_sync(0xffffffffu, m[ii], off);
            float os = __shfl_xor_sync(0xffffffffu, s[ii], off);
            float M  = fmaxf(m[ii], om);
            s[ii] = s[ii] * expf(m[ii] - M) + os * expf(om - M);
            m[ii] = M;
        }
    }
    const int warp = t >> 5, lane = t & 31;
    if (lane == 0) {
#pragma unroll
        for (int ii = 0; ii < 8; ii++) {
            red_m[warp][ii] = m[ii];
            red_s[warp][ii] = s[ii];
        }
    }
    __syncthreads();
    if (t < 8) {
        float M = red_m[0][t], S = red_s[0][t];
#pragma unroll
        for (int w = 1; w < 8; w++) {
            float om = red_m[w][t], os = red_s[w][t];
            float M2 = fmaxf(M, om);
            S = S * expf(M - M2) + os * expf(om - M2);
            M = M2;
        }
        float lse = M + logf(S);
        g_e[i0 + t] = expf(lse - logf((float)NS));
    }
}

// ---------------------------------------------------------------------------
// Final reduction: out = mean(diag) + 1 - mean(e)
// ---------------------------------------------------------------------------
__global__ __launch_bounds__(1024) void finish_kernel(float* __restrict__ out)
{
    __shared__ float sd[32];
    __shared__ float se[32];
    const int t = threadIdx.x;
    float d = g_diag[t];
    float e = g_e[t];
#pragma unroll
    for (int off = 16; off > 0; off >>= 1) {
        d += __shfl_xor_sync(0xffffffffu, d, off);
        e += __shfl_xor_sync(0xffffffffu, e, off);
    }
    const int warp = t >> 5, lane = t & 31;
    if (lane == 0) { sd[warp] = d; se[warp] = e; }
    __syncthreads();
    if (t < 32) {
        float dd = sd[t], ee = se[t];
#pragma unroll
        for (int off = 16; off > 0; off >>= 1) {
            dd += __shfl_xor_sync(0xffffffffu, dd, off);
            ee += __shfl_xor_sync(0xffffffffu, ee, off);
        }
        if (t == 0)
            out[0] = dd * (1.0f / NS) + 1.0f - ee * (1.0f / NS);
    }
}

// ---------------------------------------------------------------------------
extern "C" void kernel_launch(void* const* d_in, const int* in_sizes, int n_in,
                              void* d_out, int out_size)
{
    const float* x  = (const float*)d_in[0];
    const float* y  = (const float*)d_in[1];
    const float* W1 = (const float*)d_in[2];
    const float* b1 = (const float*)d_in[3];
    const float* W2 = (const float*)d_in[4];
    const float* b2 = (const float*)d_in[5];

    dim3 gg(NS / 64, HID / 64, 2);          // 16 x 4 x 2 = 128 blocks
    gemm_kernel<<<gg, 256>>>(x, y, W1, b1);
    pair_kernel<<<NS / 8, 256>>>(W2, b2);   // 128 blocks
    finish_kernel<<<1, 1024>>>((float*)d_out);
}

// round 2
// speedup vs baseline: 1.3354x; 1.3354x over previous
#include <cuda_runtime.h>
#include <math.h>

#define NS  1024
#define XD  128
#define HID 256

typedef unsigned long long ull;

// scratch (allocation-free rule: __device__ globals)
__device__ float g_pxT[HID * NS];   // [k][j] : px transposed
__device__ float g_pybT[HID * NS];  // [k][i] : (y@W1y + b1) transposed
__device__ float g_diag[NS];        // T1[i,i]
__device__ float g_e[NS];           // exp(lse_i - ln N)

// ---------------------------------------------------------------------------
// packed f32x2 helpers (sm_100+)
// ---------------------------------------------------------------------------
__device__ __forceinline__ ull dup2(float x) {
    ull r;
    asm("mov.b64 %0, {%1, %1};" : "=l"(r) : "f"(x));
    return r;
}

// acc2 += max(a2 + p2, 0) * w2   (elementwise on both packed lanes)
__device__ __forceinline__ void relu_fma2(ull& acc, ull a2, ull p2, ull w2) {
    asm("{\n\t"
        ".reg .b64 v;\n\t"
        ".reg .f32 lo, hi;\n\t"
        "add.rn.f32x2 v, %1, %2;\n\t"
        "mov.b64 {lo, hi}, v;\n\t"
        "max.f32 lo, lo, 0f00000000;\n\t"
        "max.f32 hi, hi, 0f00000000;\n\t"
        "mov.b64 v, {lo, hi};\n\t"
        "fma.rn.f32x2 %0, v, %3, %0;\n\t"
        "}"
        : "+l"(acc) : "l"(a2), "l"(p2), "l"(w2));
}

// ---------------------------------------------------------------------------
// GEMM: C_T[h][n] = sum_d A[n][d] * W1[z*128 + d][h]   (+ b1[h] when z==1)
// block tile 64h x 64n, 256 threads, contiguous 4x4 thread tile,
// both smem operands read via LDS.128.
// ---------------------------------------------------------------------------
__global__ __launch_bounds__(256) void gemm_kernel(
    const float* __restrict__ X, const float* __restrict__ Y,
    const float* __restrict__ W1, const float* __restrict__ b1)
{
    const int z  = blockIdx.z;
    const float* A = z ? Y : X;
    float* C = z ? g_pybT : g_pxT;
    const int h0 = blockIdx.y * 64;
    const int n0 = blockIdx.x * 64;
    const int t  = threadIdx.x;
    const int tx = t & 15;   // n quad index
    const int ty = t >> 4;   // h quad index

    __shared__ float xs[64][68];  // [d][n]  pad 68: rows 16B-aligned, odd%32 stride
    __shared__ float ws[64][64];  // [d][h]

    float acc[4][4];              // [h][n]
#pragma unroll
    for (int i = 0; i < 4; i++)
#pragma unroll
        for (int j = 0; j < 4; j++) acc[i][j] = 0.f;

    for (int k0 = 0; k0 < XD; k0 += 64) {
        __syncthreads();
        // xs: read A coalesced in d, store transposed [d][n]
#pragma unroll
        for (int r = 0; r < 16; r++) {
            int f = t + 256 * r;
            int n = f >> 6, d = f & 63;
            xs[d][n] = A[(n0 + n) * XD + k0 + d];
        }
        // ws: vectorized coalesced copy
#pragma unroll
        for (int r = 0; r < 4; r++) {
            int f = t + 256 * r;
            int d = f >> 4, h4 = (f & 15) * 4;
            *(float4*)&ws[d][h4] =
                *(const float4*)&W1[(z * XD + k0 + d) * HID + h0 + h4];
        }
        __syncthreads();
#pragma unroll 8
        for (int d = 0; d < 64; d++) {
            float4 a = *(const float4*)&ws[d][ty * 4];
            float4 b = *(const float4*)&xs[d][tx * 4];
            const float av[4] = {a.x, a.y, a.z, a.w};
            const float bv[4] = {b.x, b.y, b.z, b.w};
#pragma unroll
            for (int i = 0; i < 4; i++)
#pragma unroll
                for (int j = 0; j < 4; j++)
                    acc[i][j] = fmaf(av[i], bv[j], acc[i][j]);
        }
    }

#pragma unroll
    for (int i = 0; i < 4; i++) {
        int h = h0 + ty * 4 + i;
        float bias = z ? b1[h] : 0.f;
        float4 o = make_float4(acc[i][0] + bias, acc[i][1] + bias,
                               acc[i][2] + bias, acc[i][3] + bias);
        *(float4*)&C[h * NS + n0 + tx * 4] = o;
    }
}

// ---------------------------------------------------------------------------
// Pair kernel: block = 8 rows (i), all 1024 cols (j). 256 threads, each owns
// 8i x 4j (= 2 packed j-pairs) accumulators. Packed f32x2 math, pre-duplicated
// pyb/W2 in smem, double-buffered px LDG.128 prefetch.
// ---------------------------------------------------------------------------
__global__ __launch_bounds__(256) void pair_kernel(
    const float* __restrict__ W2, const float* __restrict__ b2)
{
    __shared__ ull sm_py2[HID][8];    // dup'd pyb_T[k][ii] = {v,v}
    __shared__ ull sm_w2[HID];        // dup'd W2
    __shared__ float red_m[8][8];     // [warp][ii]
    __shared__ float red_s[8][8];

    const int t  = threadIdx.x;
    const int i0 = blockIdx.x * 8;

    // one-time: duplicate pyb columns + W2 into packed smem
#pragma unroll
    for (int r = 0; r < 8; r++) {
        int f = t + 256 * r;          // 2048 entries
        int k = f >> 3, ii = f & 7;
        sm_py2[k][ii] = dup2(g_pybT[k * NS + i0 + ii]);
    }
    sm_w2[t] = dup2(W2[t]);           // blockDim == HID == 256
    __syncthreads();

    ull acc2[8][2];
#pragma unroll
    for (int ii = 0; ii < 8; ii++) { acc2[ii][0] = 0ull; acc2[ii][1] = 0ull; }

    // px rows as 16B chunks: each = 2 packed j-pairs = this thread's 4 j's
    const ulonglong2* px2 = (const ulonglong2*)g_pxT;   // row k: NS/4 chunks

    ulonglong2 buf[2][4];
#pragma unroll
    for (int kk = 0; kk < 4; kk++)
        buf[0][kk] = px2[kk * (NS / 4) + t];

#pragma unroll 1
    for (int k0 = 0; k0 < HID; k0 += 4) {
        const int cur = (k0 >> 2) & 1, nxt = cur ^ 1;
        const int kn = (k0 + 4) & (HID - 1);   // wraps at end (harmless)
#pragma unroll
        for (int kk = 0; kk < 4; kk++)
            buf[nxt][kk] = px2[(kn + kk) * (NS / 4) + t];

#pragma unroll
        for (int kk = 0; kk < 4; kk++) {
            const ull w2v = sm_w2[k0 + kk];
            const ulonglong2 p = buf[cur][kk];
#pragma unroll
            for (int q = 0; q < 4; q++) {      // ii pairs via LDS.128
                ulonglong2 a2q =
                    *(const ulonglong2*)&sm_py2[k0 + kk][2 * q];
                relu_fma2(acc2[2 * q][0],     a2q.x, p.x, w2v);
                relu_fma2(acc2[2 * q][1],     a2q.x, p.y, w2v);
                relu_fma2(acc2[2 * q + 1][0], a2q.y, p.x, w2v);
                relu_fma2(acc2[2 * q + 1][1], a2q.y, p.y, w2v);
            }
        }
    }

    // epilogue: T1 = acc + b2 - 1 ; diagonal capture + per-i logsumexp
    const float bm1 = b2[0] - 1.0f;
    float m[8], s[8];
    union cvt { ull u; float2 f; };
#pragma unroll
    for (int ii = 0; ii < 8; ii++) {
        cvt c0, c1;
        c0.u = acc2[ii][0];
        c1.u = acc2[ii][1];
        float v[4] = {c0.f.x + bm1, c0.f.y + bm1, c1.f.x + bm1, c1.f.y + bm1};
        const int ig = i0 + ii;
#pragma unroll
        for (int jj = 0; jj < 4; jj++)
            if (4 * t + jj == ig) g_diag[ig] = v[jj];
        float mm = fmaxf(fmaxf(v[0], v[1]), fmaxf(v[2], v[3]));
        float ss = expf(v[0] - mm) + expf(v[1] - mm) +
                   expf(v[2] - mm) + expf(v[3] - mm);
        m[ii] = mm; s[ii] = ss;
    }

    // warp-level (m,s) merge
#pragma unroll
    for (int off = 16; off > 0; off >>= 1) {
#pragma unroll
        for (int ii = 0; ii < 8; ii++) {
            float om = __shfl_xor_sync(0xffffffffu, m[ii], off);
            float os = __shfl_xor_sync(0xffffffffu, s[ii], off);
            float M  = fmaxf(m[ii], om);
            s[ii] = s[ii] * expf(m[ii] - M) + os * expf(om - M);
            m[ii] = M;
        }
    }
    const int warp = t >> 5, lane = t & 31;
    if (lane == 0) {
#pragma unroll
        for (int ii = 0; ii < 8; ii++) {
            red_m[warp][ii] = m[ii];
            red_s[warp][ii] = s[ii];
        }
    }
    __syncthreads();
    if (t < 8) {
        float M = red_m[0][t], S = red_s[0][t];
#pragma unroll
        for (int w = 1; w < 8; w++) {
            float om = red_m[w][t], os = red_s[w][t];
            float M2 = fmaxf(M, om);
            S = S * expf(M - M2) + os * expf(om - M2);
            M = M2;
        }
        float lse = M + logf(S);
        g_e[i0 + t] = expf(lse - logf((float)NS));
    }
}

// ---------------------------------------------------------------------------
// Final reduction: out = mean(diag) + 1 - mean(e)
// ---------------------------------------------------------------------------
__global__ __launch_bounds__(1024) void finish_kernel(float* __restrict__ out)
{
    __shared__ float sd[32];
    __shared__ float se[32];
    const int t = threadIdx.x;
    float d = g_diag[t];
    float e = g_e[t];
#pragma unroll
    for (int off = 16; off > 0; off >>= 1) {
        d += __shfl_xor_sync(0xffffffffu, d, off);
        e += __shfl_xor_sync(0xffffffffu, e, off);
    }
    const int warp = t >> 5, lane = t & 31;
    if (lane == 0) { sd[warp] = d; se[warp] = e; }
    __syncthreads();
    if (t < 32) {
        float dd = sd[t], ee = se[t];
#pragma unroll
        for (int off = 16; off > 0; off >>= 1) {
            dd += __shfl_xor_sync(0xffffffffu, dd, off);
            ee += __shfl_xor_sync(0xffffffffu, ee, off);
        }
        if (t == 0)
            out[0] = dd * (1.0f / NS) + 1.0f - ee * (1.0f / NS);
    }
}

// ---------------------------------------------------------------------------
extern "C" void kernel_launch(void* const* d_in, const int* in_sizes, int n_in,
                              void* d_out, int out_size)
{
    const float* x  = (const float*)d_in[0];
    const float* y  = (const float*)d_in[1];
    const float* W1 = (const float*)d_in[2];
    const float* b1 = (const float*)d_in[3];
    const float* W2 = (const float*)d_in[4];
    const float* b2 = (const float*)d_in[5];

    dim3 gg(NS / 64, HID / 64, 2);          // 16 x 4 x 2 = 128 blocks
    gemm_kernel<<<gg, 256>>>(x, y, W1, b1);
    pair_kernel<<<NS / 8, 256>>>(W2, b2);   // 128 blocks
    finish_kernel<<<1, 1024>>>((float*)d_out);
}